// round 1
// baseline (speedup 1.0000x reference)
#include <cuda_runtime.h>
#include <math.h>

// Problem constants
constexpr int BATCH = 2, SEQ = 2048, HID = 2048;
constexpr int NHEADS = 16, GRP = 4, HDIM = 128;
constexpr int MROWS = BATCH * SEQ;        // 4096
constexpr int KVDIM = GRP * HDIM;         // 512

// Scratch (device globals: no allocation allowed in kernel_launch)
__device__ float g_Q[MROWS * HID];        // 32 MB
__device__ float g_K[MROWS * KVDIM];      // 8 MB
__device__ float g_V[MROWS * KVDIM];      // 8 MB
__device__ float g_O[MROWS * HID];        // 32 MB

// ---------------------------------------------------------------------------
// SGEMM: C[M,N] = A[M,K] @ W[K,N] + bias[N]
// 128x128 block tile, BK=8, 256 threads, 8x8 register tile per thread.
// All shapes here are multiples of the tile sizes -> no bounds checks.
// ---------------------------------------------------------------------------
__global__ __launch_bounds__(256, 2)
void sgemm_bias_kernel(const float* __restrict__ A, const float* __restrict__ W,
                       const float* __restrict__ bias, float* __restrict__ C,
                       int M, int N, int K)
{
    __shared__ float Ast[8][128];   // transposed A tile: Ast[k][m]
    __shared__ float Bs[8][128];    // Bs[k][n]

    const int tid = threadIdx.x;
    const int tx = tid & 15;        // 0..15 (N dim)
    const int ty = tid >> 4;        // 0..15 (M dim)
    const int bx = blockIdx.x;      // N / 128
    const int by = blockIdx.y;      // M / 128

    const int ar = tid >> 1;            // 0..127 row within A tile
    const int ak = (tid & 1) * 4;       // 0 or 4
    const int br = tid >> 5;            // 0..7 row within B tile
    const int bc = (tid & 31) * 4;      // 0..124

    const float* Aptr = A + (size_t)(by * 128 + ar) * K + ak;
    const float* Wptr = W + (size_t)br * N + bx * 128 + bc;

    float acc[8][8];
#pragma unroll
    for (int i = 0; i < 8; i++)
#pragma unroll
        for (int j = 0; j < 8; j++) acc[i][j] = 0.f;

    for (int k0 = 0; k0 < K; k0 += 8) {
        float4 a = *(const float4*)(Aptr + k0);
        float4 b = *(const float4*)(Wptr + (size_t)k0 * N);
        __syncthreads();
        Ast[ak + 0][ar] = a.x;
        Ast[ak + 1][ar] = a.y;
        Ast[ak + 2][ar] = a.z;
        Ast[ak + 3][ar] = a.w;
        *(float4*)&Bs[br][bc] = b;
        __syncthreads();

#pragma unroll
        for (int k = 0; k < 8; k++) {
            float av[8], bv[8];
            *(float4*)(av)     = *(const float4*)&Ast[k][ty * 4];
            *(float4*)(av + 4) = *(const float4*)&Ast[k][64 + ty * 4];
            *(float4*)(bv)     = *(const float4*)&Bs[k][tx * 4];
            *(float4*)(bv + 4) = *(const float4*)&Bs[k][64 + tx * 4];
#pragma unroll
            for (int i = 0; i < 8; i++)
#pragma unroll
                for (int j = 0; j < 8; j++)
                    acc[i][j] += av[i] * bv[j];
        }
    }

    // Epilogue: add bias, store
#pragma unroll
    for (int ih = 0; ih < 2; ih++) {
#pragma unroll
        for (int i = 0; i < 4; i++) {
            int row = by * 128 + ih * 64 + ty * 4 + i;
#pragma unroll
            for (int jh = 0; jh < 2; jh++) {
                int col = bx * 128 + jh * 64 + tx * 4;
                float4 bb = *(const float4*)&bias[col];
                float4 o;
                o.x = acc[ih * 4 + i][jh * 4 + 0] + bb.x;
                o.y = acc[ih * 4 + i][jh * 4 + 1] + bb.y;
                o.z = acc[ih * 4 + i][jh * 4 + 2] + bb.z;
                o.w = acc[ih * 4 + i][jh * 4 + 3] + bb.w;
                *(float4*)&C[(size_t)row * N + col] = o;
            }
        }
    }
}

// ---------------------------------------------------------------------------
// Flash attention (causal GQA), fp32.
// Block: one (b, head, 64-row Q tile). 256 threads; 4 threads per Q row.
// K/V tiles of 64 rows streamed through smem.
// Thread (r, q): scores for columns c = cc*4+q (cc<16),
//                output slice d = dd*16 + q*4 + j (dd<8, j<4).
// ---------------------------------------------------------------------------
constexpr int PADK = 132;   // row pitch (floats) for Q/K/V smem tiles
constexpr int PADP = 65;    // row pitch for P tile
constexpr float SM_SCALE = 0.08838834764831845f;  // 1/sqrt(128)

__global__ __launch_bounds__(256, 1)
void flash_kernel(const float* __restrict__ Qg, const float* __restrict__ Kg,
                  const float* __restrict__ Vg, float* __restrict__ Og)
{
    extern __shared__ float sm[];
    float* Qs = sm;                     // 64 * PADK
    float* Ks = Qs + 64 * PADK;
    float* Vs = Ks + 64 * PADK;
    float* Ps = Vs + 64 * PADK;         // 64 * PADP

    const int t = threadIdx.x;
    const int qt = blockIdx.x;          // Q tile (0..31)
    const int h  = blockIdx.y;          // head (0..15)
    const int b  = blockIdx.z;          // batch
    const int g  = h >> 2;              // KV group (npg = 4)
    const int r  = t >> 2;              // Q row within tile
    const int q  = t & 3;               // quarter

    // Load Q tile (64 x 128) into smem
    const float* Qbase = Qg + (size_t)(b * SEQ + qt * 64) * HID + h * HDIM;
    for (int idx = t; idx < 64 * 32; idx += 256) {
        int row = idx >> 5, d4 = idx & 31;
        *(float4*)&Qs[row * PADK + d4 * 4] =
            *(const float4*)(Qbase + (size_t)row * HID + d4 * 4);
    }

    float o_acc[32];
#pragma unroll
    for (int i = 0; i < 32; i++) o_acc[i] = 0.f;
    float m = -INFINITY, l = 0.f;

    const float* Kbase = Kg + (size_t)(b * SEQ) * KVDIM + g * HDIM;
    const float* Vbase = Vg + (size_t)(b * SEQ) * KVDIM + g * HDIM;
    const int i_glob = qt * 64 + r;

    for (int kt = 0; kt <= qt; kt++) {
        __syncthreads();   // previous-tile smem reads done before overwrite
        for (int idx = t; idx < 64 * 32; idx += 256) {
            int row = idx >> 5, d4 = idx & 31;
            int grow = kt * 64 + row;
            *(float4*)&Ks[row * PADK + d4 * 4] =
                *(const float4*)(Kbase + (size_t)grow * KVDIM + d4 * 4);
            *(float4*)&Vs[row * PADK + d4 * 4] =
                *(const float4*)(Vbase + (size_t)grow * KVDIM + d4 * 4);
        }
        __syncthreads();

        // S = Q K^T for this tile: thread covers 16 columns
        float s[16];
#pragma unroll
        for (int cc = 0; cc < 16; cc++) s[cc] = 0.f;
#pragma unroll 4
        for (int d4 = 0; d4 < 32; d4++) {
            float4 qv = *(const float4*)&Qs[r * PADK + d4 * 4];
#pragma unroll
            for (int cc = 0; cc < 16; cc++) {
                float4 kv = *(const float4*)&Ks[(cc * 4 + q) * PADK + d4 * 4];
                s[cc] += qv.x * kv.x + qv.y * kv.y + qv.z * kv.z + qv.w * kv.w;
            }
        }

        // scale + causal mask
#pragma unroll
        for (int cc = 0; cc < 16; cc++) {
            int j_glob = kt * 64 + cc * 4 + q;
            s[cc] = (j_glob > i_glob) ? -1e9f : s[cc] * SM_SCALE;
        }

        // online softmax: row max / sum across 16 cols x 4 lanes
        float mloc = s[0];
#pragma unroll
        for (int cc = 1; cc < 16; cc++) mloc = fmaxf(mloc, s[cc]);
        mloc = fmaxf(mloc, __shfl_xor_sync(0xffffffffu, mloc, 1));
        mloc = fmaxf(mloc, __shfl_xor_sync(0xffffffffu, mloc, 2));
        float m_new = fmaxf(m, mloc);
        float alpha = __expf(m - m_new);

        float psum = 0.f;
#pragma unroll
        for (int cc = 0; cc < 16; cc++) {
            float p = __expf(s[cc] - m_new);
            psum += p;
            Ps[r * PADP + cc * 4 + q] = p;
        }
        psum += __shfl_xor_sync(0xffffffffu, psum, 1);
        psum += __shfl_xor_sync(0xffffffffu, psum, 2);
        l = l * alpha + psum;
        m = m_new;

#pragma unroll
        for (int i = 0; i < 32; i++) o_acc[i] *= alpha;
        __syncwarp();   // P written/read within same warp groups of 4

        // O += P @ V : thread covers d = dd*16 + q*4 + j
#pragma unroll 2
        for (int c = 0; c < 64; c++) {
            float p = Ps[r * PADP + c];
            const float* vrow = &Vs[c * PADK + q * 4];
#pragma unroll
            for (int dd = 0; dd < 8; dd++) {
                float4 vv = *(const float4*)(vrow + dd * 16);
                o_acc[dd * 4 + 0] += p * vv.x;
                o_acc[dd * 4 + 1] += p * vv.y;
                o_acc[dd * 4 + 2] += p * vv.z;
                o_acc[dd * 4 + 3] += p * vv.w;
            }
        }
    }

    float rl = 1.f / l;
    float* Out = Og + (size_t)(b * SEQ + qt * 64 + r) * HID + h * HDIM + q * 4;
#pragma unroll
    for (int dd = 0; dd < 8; dd++) {
        float4 o;
        o.x = o_acc[dd * 4 + 0] * rl;
        o.y = o_acc[dd * 4 + 1] * rl;
        o.z = o_acc[dd * 4 + 2] * rl;
        o.w = o_acc[dd * 4 + 3] * rl;
        *(float4*)(Out + dd * 16) = o;
    }
}

// ---------------------------------------------------------------------------
// Launch
// ---------------------------------------------------------------------------
extern "C" void kernel_launch(void* const* d_in, const int* in_sizes, int n_in,
                              void* d_out, int out_size)
{
    const float* x  = (const float*)d_in[0];
    // d_in[1] = causal_mask (structure known: strict upper triangular) — unused
    const float* Wq = (const float*)d_in[2];
    const float* bq = (const float*)d_in[3];
    const float* Wk = (const float*)d_in[4];
    const float* bk = (const float*)d_in[5];
    const float* Wv = (const float*)d_in[6];
    const float* bv = (const float*)d_in[7];
    const float* Wo = (const float*)d_in[8];
    const float* bo = (const float*)d_in[9];
    float* out = (float*)d_out;

    float *Qb, *Kb, *Vb, *Ob;
    cudaGetSymbolAddress((void**)&Qb, g_Q);
    cudaGetSymbolAddress((void**)&Kb, g_K);
    cudaGetSymbolAddress((void**)&Vb, g_V);
    cudaGetSymbolAddress((void**)&Ob, g_O);

    constexpr int FLASH_SMEM = (3 * 64 * PADK + 64 * PADP) * (int)sizeof(float);
    cudaFuncSetAttribute(flash_kernel,
                         cudaFuncAttributeMaxDynamicSharedMemorySize, FLASH_SMEM);

    dim3 blk(256);
    dim3 gQ(HID / 128, MROWS / 128);    // (16, 32)
    dim3 gKV(KVDIM / 128, MROWS / 128); // (4, 32)

    sgemm_bias_kernel<<<gQ, blk>>>(x, Wq, bq, Qb, MROWS, HID, HID);
    sgemm_bias_kernel<<<gKV, blk>>>(x, Wk, bk, Kb, MROWS, KVDIM, HID);
    sgemm_bias_kernel<<<gKV, blk>>>(x, Wv, bv, Vb, MROWS, KVDIM, HID);

    dim3 gF(SEQ / 64, NHEADS, BATCH);   // (32, 16, 2)
    flash_kernel<<<gF, blk, FLASH_SMEM>>>(Qb, Kb, Vb, Ob);

    sgemm_bias_kernel<<<gQ, blk>>>(Ob, Wo, bo, out, MROWS, HID, HID);
}

// round 3
// speedup vs baseline: 1.3662x; 1.3662x over previous
#include <cuda_runtime.h>
#include <cuda_bf16.h>
#include <math.h>
#include <stdint.h>

// Problem constants
constexpr int BATCH = 2, SEQ = 2048, HID = 2048;
constexpr int NHEADS = 16, GRP = 4, HDIM = 128;
constexpr int MROWS = BATCH * SEQ;        // 4096
constexpr int KVDIM = GRP * HDIM;         // 512

// ---------------------------------------------------------------------------
// Device-global scratch (no allocations allowed)
// ---------------------------------------------------------------------------
__device__ float g_Q[MROWS * HID];
__device__ float g_K[MROWS * KVDIM];
__device__ float g_V[MROWS * KVDIM];
__device__ float g_O[MROWS * HID];

__device__ __nv_bfloat16 g_Xhi[MROWS * HID];
__device__ __nv_bfloat16 g_Xlo[MROWS * HID];
__device__ __nv_bfloat16 g_Ohi[MROWS * HID];
__device__ __nv_bfloat16 g_Olo[MROWS * HID];
// Transposed weights, [N][K] K-major
__device__ __nv_bfloat16 g_WqThi[HID * HID];
__device__ __nv_bfloat16 g_WqTlo[HID * HID];
__device__ __nv_bfloat16 g_WkThi[KVDIM * HID];
__device__ __nv_bfloat16 g_WkTlo[KVDIM * HID];
__device__ __nv_bfloat16 g_WvThi[KVDIM * HID];
__device__ __nv_bfloat16 g_WvTlo[KVDIM * HID];
__device__ __nv_bfloat16 g_WoThi[HID * HID];
__device__ __nv_bfloat16 g_WoTlo[HID * HID];

// ---------------------------------------------------------------------------
// Helpers
// ---------------------------------------------------------------------------
__device__ __forceinline__ uint32_t smem_u32(const void* p) {
    uint32_t a;
    asm("{ .reg .u64 t; cvta.to.shared.u64 t, %1; cvt.u32.u64 %0, t; }"
        : "=r"(a) : "l"(p));
    return a;
}
__device__ __forceinline__ uint32_t lds32(uint32_t addr) {
    uint32_t v;
    asm volatile("ld.shared.b32 %0, [%1];" : "=r"(v) : "r"(addr));
    return v;
}
__device__ __forceinline__ void cp16(uint32_t saddr, const void* gaddr) {
    asm volatile("cp.async.cg.shared.global [%0], [%1], 16;"
                 :: "r"(saddr), "l"(gaddr));
}
__device__ __forceinline__ void mma_bf16(float* c, const uint32_t* a, const uint32_t* b) {
    asm volatile("mma.sync.aligned.m16n8k16.row.col.f32.bf16.bf16.f32 "
                 "{%0,%1,%2,%3}, {%4,%5,%6,%7}, {%8,%9}, {%0,%1,%2,%3};"
                 : "+f"(c[0]), "+f"(c[1]), "+f"(c[2]), "+f"(c[3])
                 : "r"(a[0]), "r"(a[1]), "r"(a[2]), "r"(a[3]),
                   "r"(b[0]), "r"(b[1]));
}

// ---------------------------------------------------------------------------
// Split fp32 -> hi/lo bf16
// ---------------------------------------------------------------------------
__global__ __launch_bounds__(256)
void split_kernel(const float* __restrict__ x, __nv_bfloat16* __restrict__ hi,
                  __nv_bfloat16* __restrict__ lo, int n4)
{
    int i = blockIdx.x * blockDim.x + threadIdx.x;
    if (i >= n4) return;
    float4 v = ((const float4*)x)[i];
    __nv_bfloat16 h0 = __float2bfloat16(v.x), h1 = __float2bfloat16(v.y);
    __nv_bfloat16 h2 = __float2bfloat16(v.z), h3 = __float2bfloat16(v.w);
    __nv_bfloat162 H0(h0, h1), H1(h2, h3);
    __nv_bfloat162 L0(__float2bfloat16(v.x - __bfloat162float(h0)),
                      __float2bfloat16(v.y - __bfloat162float(h1)));
    __nv_bfloat162 L1(__float2bfloat16(v.z - __bfloat162float(h2)),
                      __float2bfloat16(v.w - __bfloat162float(h3)));
    ((__nv_bfloat162*)hi)[i * 2 + 0] = H0;
    ((__nv_bfloat162*)hi)[i * 2 + 1] = H1;
    ((__nv_bfloat162*)lo)[i * 2 + 0] = L0;
    ((__nv_bfloat162*)lo)[i * 2 + 1] = L1;
}

// ---------------------------------------------------------------------------
// Transpose W[K][N] -> T[N][K] with hi/lo bf16 split
// ---------------------------------------------------------------------------
__global__ __launch_bounds__(256)
void transpose_split_kernel(const float* __restrict__ W,
                            __nv_bfloat16* __restrict__ Thi,
                            __nv_bfloat16* __restrict__ Tlo, int K, int N)
{
    __shared__ float tile[32][33];
    int n0 = blockIdx.x * 32, k0 = blockIdx.y * 32;
    int tx = threadIdx.x & 31, ty = threadIdx.x >> 5;   // 32 x 8
    for (int j = ty; j < 32; j += 8)
        tile[j][tx] = W[(size_t)(k0 + j) * N + n0 + tx];
    __syncthreads();
    for (int j = ty; j < 32; j += 8) {
        float v = tile[tx][j];                           // W[k0+tx][n0+j]
        __nv_bfloat16 h = __float2bfloat16(v);
        size_t o = (size_t)(n0 + j) * K + k0 + tx;
        Thi[o] = h;
        Tlo[o] = __float2bfloat16(v - __bfloat162float(h));
    }
}

// ---------------------------------------------------------------------------
// HMMA GEMM: C[M,N] = (Ahi+Alo)[M,K] @ (Bhi+Blo)[N,K]^T + bias
// 128x128 CTA tile, 8 warps (2M x 4N), warp tile 64x32, mma.m16n8k16 bf16.
// BK=32, cp.async double buffer. 3-term bf16 split, fp32 accumulation.
// Smem row stride = 40 bf16 (80 B): fragment quads hit all 32 banks once.
// ---------------------------------------------------------------------------
constexpr int BK = 32;
constexpr int RSTRIDE = 40;                  // bf16 per smem row
constexpr int TILE_ELEMS = 128 * RSTRIDE;    // per tile (Ahi/Alo/Bhi/Blo)
constexpr int GEMM_SMEM = 2 * 4 * TILE_ELEMS * 2;  // 81920 B

__global__ __launch_bounds__(256, 1)
void mma_gemm_kernel(const __nv_bfloat16* __restrict__ Ahi,
                     const __nv_bfloat16* __restrict__ Alo,
                     const __nv_bfloat16* __restrict__ Bhi,
                     const __nv_bfloat16* __restrict__ Blo,
                     const float* __restrict__ bias, float* __restrict__ C,
                     int N, int K)
{
    extern __shared__ __nv_bfloat16 smg[];
    const uint32_t sbase = smem_u32(smg);
    const int tid = threadIdx.x;
    const int wid = tid >> 5, lid = tid & 31;
    const int wm = wid >> 2, wn = wid & 3;           // 2 x 4 warp grid
    const int m0 = blockIdx.y * 128, n0 = blockIdx.x * 128;

    // cp.async: thread -> tile (0:Ahi 1:Alo 2:Bhi 3:Blo), 64 threads per tile
    const int tile = tid >> 6;
    const int tl = tid & 63;
    const __nv_bfloat16* tsrc =
        (tile == 0) ? Ahi + (size_t)m0 * K :
        (tile == 1) ? Alo + (size_t)m0 * K :
        (tile == 2) ? Bhi + (size_t)n0 * K :
                      Blo + (size_t)n0 * K;

    float acc[4][4][4];
#pragma unroll
    for (int mt = 0; mt < 4; mt++)
#pragma unroll
        for (int nt = 0; nt < 4; nt++)
#pragma unroll
            for (int j = 0; j < 4; j++) acc[mt][nt][j] = 0.f;

    const int nch = K / BK;

    // --- issue chunk ch into buffer buf ---
    auto issue = [&](int ch, int buf) {
        const __nv_bfloat16* src = tsrc + ch * BK;
        uint32_t base = sbase + (uint32_t)(buf * 4 + tile) * TILE_ELEMS * 2;
#pragma unroll
        for (int it = 0; it < 8; it++) {
            int o = tl + it * 64;          // 0..511
            int row = o >> 2, seg = o & 3; // 4 x 16B segs per 64B row
            cp16(base + row * 80 + seg * 16, src + (size_t)row * K + seg * 8);
        }
        asm volatile("cp.async.commit_group;" ::: "memory");
    };

    issue(0, 0);

    const int rq = lid >> 2;               // 0..7
    const int cb = (lid & 3) * 4;          // byte offset of k-pair

    for (int ch = 0; ch < nch; ch++) {
        const int buf = ch & 1;
        if (ch + 1 < nch) {
            issue(ch + 1, buf ^ 1);
            asm volatile("cp.async.wait_group 1;" ::: "memory");
        } else {
            asm volatile("cp.async.wait_group 0;" ::: "memory");
        }
        __syncthreads();

        // 3 split terms: (Ahi,Bhi), (Ahi,Blo), (Alo,Bhi)
        const uint32_t aoff[3] = {0, 0, 1}, boff[3] = {2, 3, 2};
#pragma unroll
        for (int t = 0; t < 3; t++) {
            uint32_t As = sbase + (uint32_t)(buf * 4 + aoff[t]) * TILE_ELEMS * 2
                        + (wm * 64) * 80;
            uint32_t Bs = sbase + (uint32_t)(buf * 4 + boff[t]) * TILE_ELEMS * 2
                        + (wn * 32) * 80;
#pragma unroll
            for (int ks = 0; ks < 2; ks++) {
                const uint32_t kb = ks * 32 + cb;   // byte col offset
                uint32_t a[4][4], b[4][2];
#pragma unroll
                for (int mt = 0; mt < 4; mt++) {
                    uint32_t r0 = As + (mt * 16 + rq) * 80 + kb;
                    a[mt][0] = lds32(r0);
                    a[mt][1] = lds32(r0 + 8 * 80);
                    a[mt][2] = lds32(r0 + 16);
                    a[mt][3] = lds32(r0 + 8 * 80 + 16);
                }
#pragma unroll
                for (int nt = 0; nt < 4; nt++) {
                    uint32_t r = Bs + (nt * 8 + rq) * 80 + kb;
                    b[nt][0] = lds32(r);
                    b[nt][1] = lds32(r + 16);
                }
#pragma unroll
                for (int mt = 0; mt < 4; mt++)
#pragma unroll
                    for (int nt = 0; nt < 4; nt++)
                        mma_bf16(acc[mt][nt], a[mt], b[nt]);
            }
        }
        __syncthreads();
    }

    // Epilogue
    const int rbase = m0 + wm * 64 + rq;
    const int cbase = n0 + wn * 32 + (lid & 3) * 2;
#pragma unroll
    for (int mt = 0; mt < 4; mt++) {
#pragma unroll
        for (int nt = 0; nt < 4; nt++) {
            int r = rbase + mt * 16;
            int c = cbase + nt * 8;
            float bx = __ldg(&bias[c]), by = __ldg(&bias[c + 1]);
            float2 o0 = make_float2(acc[mt][nt][0] + bx, acc[mt][nt][1] + by);
            float2 o1 = make_float2(acc[mt][nt][2] + bx, acc[mt][nt][3] + by);
            *(float2*)&C[(size_t)r * N + c] = o0;
            *(float2*)&C[(size_t)(r + 8) * N + c] = o1;
        }
    }
}

// ---------------------------------------------------------------------------
// Flash attention (causal GQA), fp32 — unchanged from round 1.
// ---------------------------------------------------------------------------
constexpr int PADK = 132;
constexpr int PADP = 65;
constexpr float SM_SCALE = 0.08838834764831845f;   // 1/sqrt(128)

__global__ __launch_bounds__(256, 1)
void flash_kernel(const float* __restrict__ Qg, const float* __restrict__ Kg,
                  const float* __restrict__ Vg, float* __restrict__ Og)
{
    extern __shared__ float smf[];
    float* Qs = smf;
    float* Ks = Qs + 64 * PADK;
    float* Vs = Ks + 64 * PADK;
    float* Ps = Vs + 64 * PADK;

    const int t = threadIdx.x;
    const int qt = blockIdx.x;
    const int h  = blockIdx.y;
    const int b  = blockIdx.z;
    const int g  = h >> 2;
    const int r  = t >> 2;
    const int q  = t & 3;

    const float* Qbase = Qg + (size_t)(b * SEQ + qt * 64) * HID + h * HDIM;
    for (int idx = t; idx < 64 * 32; idx += 256) {
        int row = idx >> 5, d4 = idx & 31;
        *(float4*)&Qs[row * PADK + d4 * 4] =
            *(const float4*)(Qbase + (size_t)row * HID + d4 * 4);
    }

    float o_acc[32];
#pragma unroll
    for (int i = 0; i < 32; i++) o_acc[i] = 0.f;
    float m = -INFINITY, l = 0.f;

    const float* Kbase = Kg + (size_t)(b * SEQ) * KVDIM + g * HDIM;
    const float* Vbase = Vg + (size_t)(b * SEQ) * KVDIM + g * HDIM;
    const int i_glob = qt * 64 + r;

    for (int kt = 0; kt <= qt; kt++) {
        __syncthreads();
        for (int idx = t; idx < 64 * 32; idx += 256) {
            int row = idx >> 5, d4 = idx & 31;
            int grow = kt * 64 + row;
            *(float4*)&Ks[row * PADK + d4 * 4] =
                *(const float4*)(Kbase + (size_t)grow * KVDIM + d4 * 4);
            *(float4*)&Vs[row * PADK + d4 * 4] =
                *(const float4*)(Vbase + (size_t)grow * KVDIM + d4 * 4);
        }
        __syncthreads();

        float s[16];
#pragma unroll
        for (int cc = 0; cc < 16; cc++) s[cc] = 0.f;
#pragma unroll 4
        for (int d4 = 0; d4 < 32; d4++) {
            float4 qv = *(const float4*)&Qs[r * PADK + d4 * 4];
#pragma unroll
            for (int cc = 0; cc < 16; cc++) {
                float4 kv = *(const float4*)&Ks[(cc * 4 + q) * PADK + d4 * 4];
                s[cc] += qv.x * kv.x + qv.y * kv.y + qv.z * kv.z + qv.w * kv.w;
            }
        }
#pragma unroll
        for (int cc = 0; cc < 16; cc++) {
            int j_glob = kt * 64 + cc * 4 + q;
            s[cc] = (j_glob > i_glob) ? -1e9f : s[cc] * SM_SCALE;
        }
        float mloc = s[0];
#pragma unroll
        for (int cc = 1; cc < 16; cc++) mloc = fmaxf(mloc, s[cc]);
        mloc = fmaxf(mloc, __shfl_xor_sync(0xffffffffu, mloc, 1));
        mloc = fmaxf(mloc, __shfl_xor_sync(0xffffffffu, mloc, 2));
        float m_new = fmaxf(m, mloc);
        float alpha = __expf(m - m_new);

        float psum = 0.f;
#pragma unroll
        for (int cc = 0; cc < 16; cc++) {
            float p = __expf(s[cc] - m_new);
            psum += p;
            Ps[r * PADP + cc * 4 + q] = p;
        }
        psum += __shfl_xor_sync(0xffffffffu, psum, 1);
        psum += __shfl_xor_sync(0xffffffffu, psum, 2);
        l = l * alpha + psum;
        m = m_new;

#pragma unroll
        for (int i = 0; i < 32; i++) o_acc[i] *= alpha;
        __syncwarp();

#pragma unroll 2
        for (int c = 0; c < 64; c++) {
            float p = Ps[r * PADP + c];
            const float* vrow = &Vs[c * PADK + q * 4];
#pragma unroll
            for (int dd = 0; dd < 8; dd++) {
                float4 vv = *(const float4*)(vrow + dd * 16);
                o_acc[dd * 4 + 0] += p * vv.x;
                o_acc[dd * 4 + 1] += p * vv.y;
                o_acc[dd * 4 + 2] += p * vv.z;
                o_acc[dd * 4 + 3] += p * vv.w;
            }
        }
    }

    float rl = 1.f / l;
    float* Out = Og + (size_t)(b * SEQ + qt * 64 + r) * HID + h * HDIM + q * 4;
#pragma unroll
    for (int dd = 0; dd < 8; dd++) {
        float4 o;
        o.x = o_acc[dd * 4 + 0] * rl;
        o.y = o_acc[dd * 4 + 1] * rl;
        o.z = o_acc[dd * 4 + 2] * rl;
        o.w = o_acc[dd * 4 + 3] * rl;
        *(float4*)(Out + dd * 16) = o;
    }
}

// ---------------------------------------------------------------------------
// Launch
// ---------------------------------------------------------------------------
extern "C" void kernel_launch(void* const* d_in, const int* in_sizes, int n_in,
                              void* d_out, int out_size)
{
    const float* x  = (const float*)d_in[0];
    const float* Wq = (const float*)d_in[2];
    const float* bq = (const float*)d_in[3];
    const float* Wk = (const float*)d_in[4];
    const float* bk = (const float*)d_in[5];
    const float* Wv = (const float*)d_in[6];
    const float* bv = (const float*)d_in[7];
    const float* Wo = (const float*)d_in[8];
    const float* bo = (const float*)d_in[9];
    float* out = (float*)d_out;

    float *Qb, *Kb, *Vb, *Ob;
    cudaGetSymbolAddress((void**)&Qb, g_Q);
    cudaGetSymbolAddress((void**)&Kb, g_K);
    cudaGetSymbolAddress((void**)&Vb, g_V);
    cudaGetSymbolAddress((void**)&Ob, g_O);
    __nv_bfloat16 *Xhi, *Xlo, *Ohi, *Olo;
    __nv_bfloat16 *WqThi, *WqTlo, *WkThi, *WkTlo, *WvThi, *WvTlo, *WoThi, *WoTlo;
    cudaGetSymbolAddress((void**)&Xhi, g_Xhi);
    cudaGetSymbolAddress((void**)&Xlo, g_Xlo);
    cudaGetSymbolAddress((void**)&Ohi, g_Ohi);
    cudaGetSymbolAddress((void**)&Olo, g_Olo);
    cudaGetSymbolAddress((void**)&WqThi, g_WqThi);
    cudaGetSymbolAddress((void**)&WqTlo, g_WqTlo);
    cudaGetSymbolAddress((void**)&WkThi, g_WkThi);
    cudaGetSymbolAddress((void**)&WkTlo, g_WkTlo);
    cudaGetSymbolAddress((void**)&WvThi, g_WvThi);
    cudaGetSymbolAddress((void**)&WvTlo, g_WvTlo);
    cudaGetSymbolAddress((void**)&WoThi, g_WoThi);
    cudaGetSymbolAddress((void**)&WoTlo, g_WoTlo);

    cudaFuncSetAttribute(mma_gemm_kernel,
                         cudaFuncAttributeMaxDynamicSharedMemorySize, GEMM_SMEM);
    constexpr int FLASH_SMEM = (3 * 64 * PADK + 64 * PADP) * (int)sizeof(float);
    cudaFuncSetAttribute(flash_kernel,
                         cudaFuncAttributeMaxDynamicSharedMemorySize, FLASH_SMEM);

    // 1) split inputs / transpose+split weights
    split_kernel<<<(MROWS * HID / 4 + 255) / 256, 256>>>(x, Xhi, Xlo, MROWS * HID / 4);
    transpose_split_kernel<<<dim3(HID / 32, HID / 32), 256>>>(Wq, WqThi, WqTlo, HID, HID);
    transpose_split_kernel<<<dim3(KVDIM / 32, HID / 32), 256>>>(Wk, WkThi, WkTlo, HID, KVDIM);
    transpose_split_kernel<<<dim3(KVDIM / 32, HID / 32), 256>>>(Wv, WvThi, WvTlo, HID, KVDIM);
    transpose_split_kernel<<<dim3(HID / 32, HID / 32), 256>>>(Wo, WoThi, WoTlo, HID, HID);

    // 2) projections (HMMA tensor cores)
    dim3 blk(256);
    mma_gemm_kernel<<<dim3(HID / 128, MROWS / 128), blk, GEMM_SMEM>>>(
        Xhi, Xlo, WqThi, WqTlo, bq, Qb, HID, HID);
    mma_gemm_kernel<<<dim3(KVDIM / 128, MROWS / 128), blk, GEMM_SMEM>>>(
        Xhi, Xlo, WkThi, WkTlo, bk, Kb, KVDIM, HID);
    mma_gemm_kernel<<<dim3(KVDIM / 128, MROWS / 128), blk, GEMM_SMEM>>>(
        Xhi, Xlo, WvThi, WvTlo, bv, Vb, KVDIM, HID);

    // 3) attention
    flash_kernel<<<dim3(SEQ / 64, NHEADS, BATCH), blk, FLASH_SMEM>>>(Qb, Kb, Vb, Ob);

    // 4) output projection
    split_kernel<<<(MROWS * HID / 4 + 255) / 256, 256>>>(Ob, Ohi, Olo, MROWS * HID / 4);
    mma_gemm_kernel<<<dim3(HID / 128, MROWS / 128), blk, GEMM_SMEM>>>(
        Ohi, Olo, WoThi, WoTlo, bo, out, HID, HID);
}

// round 4
// speedup vs baseline: 3.2746x; 2.3968x over previous
#include <cuda_runtime.h>
#include <cuda_bf16.h>
#include <math.h>
#include <stdint.h>

// Problem constants
constexpr int BATCH = 2, SEQ = 2048, HID = 2048;
constexpr int NHEADS = 16, GRP = 4, HDIM = 128;
constexpr int MROWS = BATCH * SEQ;        // 4096
constexpr int KVDIM = GRP * HDIM;         // 512

// ---------------------------------------------------------------------------
// Device-global scratch (bf16 hi/lo everywhere; no fp32 intermediates)
// ---------------------------------------------------------------------------
__device__ __nv_bfloat16 g_Xhi[MROWS * HID];
__device__ __nv_bfloat16 g_Xlo[MROWS * HID];
__device__ __nv_bfloat16 g_Qhi[MROWS * HID];
__device__ __nv_bfloat16 g_Qlo[MROWS * HID];
__device__ __nv_bfloat16 g_Khi[MROWS * KVDIM];
__device__ __nv_bfloat16 g_Klo[MROWS * KVDIM];
__device__ __nv_bfloat16 g_Vhi[MROWS * KVDIM];
__device__ __nv_bfloat16 g_Vlo[MROWS * KVDIM];
__device__ __nv_bfloat16 g_AOhi[MROWS * HID];
__device__ __nv_bfloat16 g_AOlo[MROWS * HID];
// Transposed weights, [N][K] K-major
__device__ __nv_bfloat16 g_WqThi[HID * HID];
__device__ __nv_bfloat16 g_WqTlo[HID * HID];
__device__ __nv_bfloat16 g_WkThi[KVDIM * HID];
__device__ __nv_bfloat16 g_WkTlo[KVDIM * HID];
__device__ __nv_bfloat16 g_WvThi[KVDIM * HID];
__device__ __nv_bfloat16 g_WvTlo[KVDIM * HID];
__device__ __nv_bfloat16 g_WoThi[HID * HID];
__device__ __nv_bfloat16 g_WoTlo[HID * HID];

// ---------------------------------------------------------------------------
// Helpers
// ---------------------------------------------------------------------------
__device__ __forceinline__ uint32_t smem_u32(const void* p) {
    uint32_t a;
    asm("{ .reg .u64 t; cvta.to.shared.u64 t, %1; cvt.u32.u64 %0, t; }"
        : "=r"(a) : "l"(p));
    return a;
}
__device__ __forceinline__ uint32_t lds32(uint32_t addr) {
    uint32_t v;
    asm volatile("ld.shared.b32 %0, [%1];" : "=r"(v) : "r"(addr));
    return v;
}
__device__ __forceinline__ void cp16(uint32_t saddr, const void* gaddr) {
    asm volatile("cp.async.cg.shared.global [%0], [%1], 16;"
                 :: "r"(saddr), "l"(gaddr));
}
__device__ __forceinline__ void mma_bf16(float* c, const uint32_t* a, const uint32_t* b) {
    asm volatile("mma.sync.aligned.m16n8k16.row.col.f32.bf16.bf16.f32 "
                 "{%0,%1,%2,%3}, {%4,%5,%6,%7}, {%8,%9}, {%0,%1,%2,%3};"
                 : "+f"(c[0]), "+f"(c[1]), "+f"(c[2]), "+f"(c[3])
                 : "r"(a[0]), "r"(a[1]), "r"(a[2]), "r"(a[3]),
                   "r"(b[0]), "r"(b[1]));
}
#define LDMX4T(r0, r1, r2, r3, addr) \
    asm volatile("ldmatrix.sync.aligned.m8n8.x4.trans.shared.b16 {%0,%1,%2,%3}, [%4];" \
                 : "=r"(r0), "=r"(r1), "=r"(r2), "=r"(r3) : "r"(addr))

__device__ __forceinline__ uint32_t packbf(float x, float y) {
    __nv_bfloat162 t = __floats2bfloat162_rn(x, y);
    return *(uint32_t*)&t;
}

// ---------------------------------------------------------------------------
// Split fp32 -> hi/lo bf16 (input x only)
// ---------------------------------------------------------------------------
__global__ __launch_bounds__(256)
void split_kernel(const float* __restrict__ x, __nv_bfloat16* __restrict__ hi,
                  __nv_bfloat16* __restrict__ lo, int n4)
{
    int i = blockIdx.x * blockDim.x + threadIdx.x;
    if (i >= n4) return;
    float4 v = ((const float4*)x)[i];
    __nv_bfloat16 h0 = __float2bfloat16(v.x), h1 = __float2bfloat16(v.y);
    __nv_bfloat16 h2 = __float2bfloat16(v.z), h3 = __float2bfloat16(v.w);
    ((__nv_bfloat162*)hi)[i * 2 + 0] = __nv_bfloat162(h0, h1);
    ((__nv_bfloat162*)hi)[i * 2 + 1] = __nv_bfloat162(h2, h3);
    ((__nv_bfloat162*)lo)[i * 2 + 0] =
        __nv_bfloat162(__float2bfloat16(v.x - __bfloat162float(h0)),
                       __float2bfloat16(v.y - __bfloat162float(h1)));
    ((__nv_bfloat162*)lo)[i * 2 + 1] =
        __nv_bfloat162(__float2bfloat16(v.z - __bfloat162float(h2)),
                       __float2bfloat16(v.w - __bfloat162float(h3)));
}

// ---------------------------------------------------------------------------
// Transpose W[K][N] -> T[N][K] with hi/lo bf16 split
// ---------------------------------------------------------------------------
__global__ __launch_bounds__(256)
void transpose_split_kernel(const float* __restrict__ W,
                            __nv_bfloat16* __restrict__ Thi,
                            __nv_bfloat16* __restrict__ Tlo, int K, int N)
{
    __shared__ float tile[32][33];
    int n0 = blockIdx.x * 32, k0 = blockIdx.y * 32;
    int tx = threadIdx.x & 31, ty = threadIdx.x >> 5;
    for (int j = ty; j < 32; j += 8)
        tile[j][tx] = W[(size_t)(k0 + j) * N + n0 + tx];
    __syncthreads();
    for (int j = ty; j < 32; j += 8) {
        float v = tile[tx][j];
        __nv_bfloat16 h = __float2bfloat16(v);
        size_t o = (size_t)(n0 + j) * K + k0 + tx;
        Thi[o] = h;
        Tlo[o] = __float2bfloat16(v - __bfloat162float(h));
    }
}

// ---------------------------------------------------------------------------
// HMMA GEMM: C = (Ahi+Alo)[M,K] @ (Bhi+Blo)[N,K]^T + bias
// Template: SPLIT=false -> fp32 C; SPLIT=true -> bf16 hi/lo outputs.
// ---------------------------------------------------------------------------
constexpr int BK = 32;
constexpr int RSTRIDE = 40;
constexpr int TILE_ELEMS = 128 * RSTRIDE;
constexpr int GEMM_SMEM = 2 * 4 * TILE_ELEMS * 2;   // 81920 B

template <bool SPLIT>
__global__ __launch_bounds__(256, 1)
void mma_gemm_kernel(const __nv_bfloat16* __restrict__ Ahi,
                     const __nv_bfloat16* __restrict__ Alo,
                     const __nv_bfloat16* __restrict__ Bhi,
                     const __nv_bfloat16* __restrict__ Blo,
                     const float* __restrict__ bias,
                     float* __restrict__ C,
                     __nv_bfloat16* __restrict__ Chi,
                     __nv_bfloat16* __restrict__ Clo,
                     int N, int K)
{
    extern __shared__ __nv_bfloat16 smg[];
    const uint32_t sbase = smem_u32(smg);
    const int tid = threadIdx.x;
    const int wid = tid >> 5, lid = tid & 31;
    const int wm = wid >> 2, wn = wid & 3;
    const int m0 = blockIdx.y * 128, n0 = blockIdx.x * 128;

    const int tile = tid >> 6;
    const int tl = tid & 63;
    const __nv_bfloat16* tsrc =
        (tile == 0) ? Ahi + (size_t)m0 * K :
        (tile == 1) ? Alo + (size_t)m0 * K :
        (tile == 2) ? Bhi + (size_t)n0 * K :
                      Blo + (size_t)n0 * K;

    float acc[4][4][4];
#pragma unroll
    for (int mt = 0; mt < 4; mt++)
#pragma unroll
        for (int nt = 0; nt < 4; nt++)
#pragma unroll
            for (int j = 0; j < 4; j++) acc[mt][nt][j] = 0.f;

    const int nch = K / BK;

    auto issue = [&](int ch, int buf) {
        const __nv_bfloat16* src = tsrc + ch * BK;
        uint32_t base = sbase + (uint32_t)(buf * 4 + tile) * TILE_ELEMS * 2;
#pragma unroll
        for (int it = 0; it < 8; it++) {
            int o = tl + it * 64;
            int row = o >> 2, seg = o & 3;
            cp16(base + row * 80 + seg * 16, src + (size_t)row * K + seg * 8);
        }
        asm volatile("cp.async.commit_group;" ::: "memory");
    };

    issue(0, 0);

    const int rq = lid >> 2;
    const int cb = (lid & 3) * 4;

    for (int ch = 0; ch < nch; ch++) {
        const int buf = ch & 1;
        if (ch + 1 < nch) {
            issue(ch + 1, buf ^ 1);
            asm volatile("cp.async.wait_group 1;" ::: "memory");
        } else {
            asm volatile("cp.async.wait_group 0;" ::: "memory");
        }
        __syncthreads();

        const uint32_t aoff[3] = {0, 0, 1}, boff[3] = {2, 3, 2};
#pragma unroll
        for (int t = 0; t < 3; t++) {
            uint32_t As = sbase + (uint32_t)(buf * 4 + aoff[t]) * TILE_ELEMS * 2
                        + (wm * 64) * 80;
            uint32_t Bs = sbase + (uint32_t)(buf * 4 + boff[t]) * TILE_ELEMS * 2
                        + (wn * 32) * 80;
#pragma unroll
            for (int ks = 0; ks < 2; ks++) {
                const uint32_t kb = ks * 32 + cb;
                uint32_t a[4][4], b[4][2];
#pragma unroll
                for (int mt = 0; mt < 4; mt++) {
                    uint32_t r0 = As + (mt * 16 + rq) * 80 + kb;
                    a[mt][0] = lds32(r0);
                    a[mt][1] = lds32(r0 + 8 * 80);
                    a[mt][2] = lds32(r0 + 16);
                    a[mt][3] = lds32(r0 + 8 * 80 + 16);
                }
#pragma unroll
                for (int nt = 0; nt < 4; nt++) {
                    uint32_t r = Bs + (nt * 8 + rq) * 80 + kb;
                    b[nt][0] = lds32(r);
                    b[nt][1] = lds32(r + 16);
                }
#pragma unroll
                for (int mt = 0; mt < 4; mt++)
#pragma unroll
                    for (int nt = 0; nt < 4; nt++)
                        mma_bf16(acc[mt][nt], a[mt], b[nt]);
            }
        }
        __syncthreads();
    }

    const int rbase = m0 + wm * 64 + rq;
    const int cbase = n0 + wn * 32 + (lid & 3) * 2;
#pragma unroll
    for (int mt = 0; mt < 4; mt++) {
#pragma unroll
        for (int nt = 0; nt < 4; nt++) {
            int r = rbase + mt * 16;
            int c = cbase + nt * 8;
            float bx = __ldg(&bias[c]), by = __ldg(&bias[c + 1]);
            float v00 = acc[mt][nt][0] + bx, v01 = acc[mt][nt][1] + by;
            float v10 = acc[mt][nt][2] + bx, v11 = acc[mt][nt][3] + by;
            if (SPLIT) {
                __nv_bfloat16 h00 = __float2bfloat16(v00), h01 = __float2bfloat16(v01);
                __nv_bfloat16 h10 = __float2bfloat16(v10), h11 = __float2bfloat16(v11);
                *(__nv_bfloat162*)&Chi[(size_t)r * N + c] = __nv_bfloat162(h00, h01);
                *(__nv_bfloat162*)&Chi[(size_t)(r + 8) * N + c] = __nv_bfloat162(h10, h11);
                *(__nv_bfloat162*)&Clo[(size_t)r * N + c] =
                    __nv_bfloat162(__float2bfloat16(v00 - __bfloat162float(h00)),
                                   __float2bfloat16(v01 - __bfloat162float(h01)));
                *(__nv_bfloat162*)&Clo[(size_t)(r + 8) * N + c] =
                    __nv_bfloat162(__float2bfloat16(v10 - __bfloat162float(h10)),
                                   __float2bfloat16(v11 - __bfloat162float(h11)));
            } else {
                *(float2*)&C[(size_t)r * N + c] = make_float2(v00, v01);
                *(float2*)&C[(size_t)(r + 8) * N + c] = make_float2(v10, v11);
            }
        }
    }
}

// ---------------------------------------------------------------------------
// HMMA flash attention (causal GQA).
// CTA: 128 Q rows x one (head, batch). 8 warps, each owns 16 Q rows.
// KV tile = 64. 3-term bf16 split for both QK^T and PV, fp32 accum.
// P passes S-accum -> A-fragment in registers (no smem P).
// ---------------------------------------------------------------------------
constexpr int QT = 128, KT = 64;
constexpr int STRB = 272;                     // smem row stride bytes (136 bf16)
constexpr int OFF_QHI = 0;
constexpr int OFF_QLO = OFF_QHI + QT * STRB;  // 34816
constexpr int OFF_KHI = OFF_QLO + QT * STRB;  // 69632
constexpr int OFF_KLO = OFF_KHI + KT * STRB;  // 87040
constexpr int OFF_VHI = OFF_KLO + KT * STRB;  // 104448
constexpr int OFF_VLO = OFF_VHI + KT * STRB;  // 121856
constexpr int FLASH_SMEM = OFF_VLO + KT * STRB;  // 139264
constexpr float SM_SCALE = 0.08838834764831845f; // 1/sqrt(128)

__global__ __launch_bounds__(256, 1)
void flash_mma_kernel(const __nv_bfloat16* __restrict__ Qhi,
                      const __nv_bfloat16* __restrict__ Qlo,
                      const __nv_bfloat16* __restrict__ Khi,
                      const __nv_bfloat16* __restrict__ Klo,
                      const __nv_bfloat16* __restrict__ Vhi,
                      const __nv_bfloat16* __restrict__ Vlo,
                      __nv_bfloat16* __restrict__ Ohi,
                      __nv_bfloat16* __restrict__ Olo)
{
    extern __shared__ __nv_bfloat16 shb[];
    const uint32_t sb = smem_u32(shb);
    const int tid = threadIdx.x;
    const int w = tid >> 5, lid = tid & 31;
    const int rq = lid >> 2, cq = lid & 3;
    const int qt = blockIdx.x, h = blockIdx.y, b = blockIdx.z;
    const int g = h >> 2;
    const int q0 = qt * QT;

    // ---- load Q tile (hi+lo), 128 rows x 128 bf16 each ----
    {
        const __nv_bfloat16* srcs[2] = {Qhi, Qlo};
#pragma unroll
        for (int it = 0; it < 16; it++) {
            int idx = it * 256 + tid;             // 0..4095
            int arr = idx >> 11, rem = idx & 2047;
            int row = rem >> 4, seg = rem & 15;
            const __nv_bfloat16* gp = srcs[arr]
                + (size_t)(b * SEQ + q0 + row) * HID + h * HDIM + seg * 8;
            cp16(sb + (arr ? OFF_QLO : OFF_QHI) + row * STRB + seg * 16, gp);
        }
        asm volatile("cp.async.commit_group;" ::: "memory");
    }

    float oacc[16][4];
#pragma unroll
    for (int nt = 0; nt < 16; nt++)
#pragma unroll
        for (int j = 0; j < 4; j++) oacc[nt][j] = 0.f;
    float m0 = -INFINITY, m1 = -INFINITY, l0 = 0.f, l1 = 0.f;

    const int nkt = 2 * qt + 2;
    const int i0 = q0 + w * 16 + rq;       // global Q row (low half)

    for (int kt = 0; kt < nkt; kt++) {
        const int k0 = kt * KT;
        __syncthreads();     // prior-iteration smem reads complete
        // ---- load K/V tiles (hi+lo), 64 rows x 128 bf16 each ----
        {
            const __nv_bfloat16* srcs[4] = {Khi, Klo, Vhi, Vlo};
            const uint32_t offs[4] = {OFF_KHI, OFF_KLO, OFF_VHI, OFF_VLO};
#pragma unroll
            for (int it = 0; it < 16; it++) {
                int idx = it * 256 + tid;          // 0..4095
                int arr = idx >> 10, rem = idx & 1023;
                int row = rem >> 4, seg = rem & 15;
                const __nv_bfloat16* gp = srcs[arr]
                    + (size_t)(b * SEQ + k0 + row) * KVDIM + g * HDIM + seg * 8;
                cp16(sb + offs[arr] + row * STRB + seg * 16, gp);
            }
            asm volatile("cp.async.commit_group;" ::: "memory");
            asm volatile("cp.async.wait_group 0;" ::: "memory");
        }
        __syncthreads();

        // ---- S = Q K^T (3 split terms), 16x64 per warp ----
        float sacc[8][4];
#pragma unroll
        for (int nt = 0; nt < 8; nt++)
#pragma unroll
            for (int j = 0; j < 4; j++) sacc[nt][j] = 0.f;

#pragma unroll
        for (int ks = 0; ks < 8; ks++) {
            const uint32_t qoff = (w * 16 + rq) * STRB + ks * 32 + cq * 4;
            uint32_t aHi[4], aLo[4];
            aHi[0] = lds32(sb + OFF_QHI + qoff);
            aHi[1] = lds32(sb + OFF_QHI + qoff + 8 * STRB);
            aHi[2] = lds32(sb + OFF_QHI + qoff + 16);
            aHi[3] = lds32(sb + OFF_QHI + qoff + 8 * STRB + 16);
            aLo[0] = lds32(sb + OFF_QLO + qoff);
            aLo[1] = lds32(sb + OFF_QLO + qoff + 8 * STRB);
            aLo[2] = lds32(sb + OFF_QLO + qoff + 16);
            aLo[3] = lds32(sb + OFF_QLO + qoff + 8 * STRB + 16);
            uint32_t bHi[8][2], bLo[8][2];
#pragma unroll
            for (int nt = 0; nt < 8; nt++) {
                const uint32_t koff = (nt * 8 + rq) * STRB + ks * 32 + cq * 4;
                bHi[nt][0] = lds32(sb + OFF_KHI + koff);
                bHi[nt][1] = lds32(sb + OFF_KHI + koff + 16);
                bLo[nt][0] = lds32(sb + OFF_KLO + koff);
                bLo[nt][1] = lds32(sb + OFF_KLO + koff + 16);
            }
#pragma unroll
            for (int nt = 0; nt < 8; nt++) {
                mma_bf16(sacc[nt], aHi, bHi[nt]);
                mma_bf16(sacc[nt], aHi, bLo[nt]);
                mma_bf16(sacc[nt], aLo, bHi[nt]);
            }
        }

        // ---- scale + causal mask ----
        const bool need_mask = (kt >= nkt - 2);
#pragma unroll
        for (int nt = 0; nt < 8; nt++) {
#pragma unroll
            for (int j = 0; j < 4; j++) {
                float s = sacc[nt][j] * SM_SCALE;
                if (need_mask) {
                    int jj = k0 + nt * 8 + cq * 2 + (j & 1);
                    int ii = i0 + ((j >> 1) << 3);
                    if (jj > ii) s = -1e30f;
                }
                sacc[nt][j] = s;
            }
        }

        // ---- online softmax (rows live in lane quads) ----
        float mx0 = -INFINITY, mx1 = -INFINITY;
#pragma unroll
        for (int nt = 0; nt < 8; nt++) {
            mx0 = fmaxf(mx0, fmaxf(sacc[nt][0], sacc[nt][1]));
            mx1 = fmaxf(mx1, fmaxf(sacc[nt][2], sacc[nt][3]));
        }
        mx0 = fmaxf(mx0, __shfl_xor_sync(0xffffffffu, mx0, 1));
        mx0 = fmaxf(mx0, __shfl_xor_sync(0xffffffffu, mx0, 2));
        mx1 = fmaxf(mx1, __shfl_xor_sync(0xffffffffu, mx1, 1));
        mx1 = fmaxf(mx1, __shfl_xor_sync(0xffffffffu, mx1, 2));
        float mn0 = fmaxf(m0, mx0), mn1 = fmaxf(m1, mx1);
        float al0 = __expf(m0 - mn0), al1 = __expf(m1 - mn1);
        m0 = mn0; m1 = mn1;

        float ls0 = 0.f, ls1 = 0.f;
#pragma unroll
        for (int nt = 0; nt < 8; nt++) {
            float p0 = __expf(sacc[nt][0] - mn0);
            float p1 = __expf(sacc[nt][1] - mn0);
            float p2 = __expf(sacc[nt][2] - mn1);
            float p3 = __expf(sacc[nt][3] - mn1);
            ls0 += p0 + p1; ls1 += p2 + p3;
            sacc[nt][0] = p0; sacc[nt][1] = p1; sacc[nt][2] = p2; sacc[nt][3] = p3;
        }
        ls0 += __shfl_xor_sync(0xffffffffu, ls0, 1);
        ls0 += __shfl_xor_sync(0xffffffffu, ls0, 2);
        ls1 += __shfl_xor_sync(0xffffffffu, ls1, 1);
        ls1 += __shfl_xor_sync(0xffffffffu, ls1, 2);
        l0 = l0 * al0 + ls0;
        l1 = l1 * al1 + ls1;

#pragma unroll
        for (int nt = 0; nt < 16; nt++) {
            oacc[nt][0] *= al0; oacc[nt][1] *= al0;
            oacc[nt][2] *= al1; oacc[nt][3] *= al1;
        }

        // ---- O += P V (3 split terms) ----
#pragma unroll
        for (int ks = 0; ks < 4; ks++) {
            // A-fragments from P (registers), split hi/lo
            uint32_t aHi[4], aLo[4];
#pragma unroll
            for (int half = 0; half < 2; half++) {
                const float* p = sacc[2 * ks + half];
                float h0 = __bfloat162float(__float2bfloat16(p[0]));
                float h1 = __bfloat162float(__float2bfloat16(p[1]));
                float h2 = __bfloat162float(__float2bfloat16(p[2]));
                float h3 = __bfloat162float(__float2bfloat16(p[3]));
                aHi[2 * half + 0] = packbf(h0, h1);
                aHi[2 * half + 1] = packbf(h2, h3);
                aLo[2 * half + 0] = packbf(p[0] - h0, p[1] - h1);
                aLo[2 * half + 1] = packbf(p[2] - h2, p[3] - h3);
            }
            // Wrong ordering fix: a0,a1 are rows r/r+8 of k-cols 0..7; a2,a3 k-cols 8..15.
            // half=0 gives k-cols 0..7 -> a[0],a[1]; half=1 -> a[2],a[3].  (as coded)
#pragma unroll
            for (int ntp = 0; ntp < 8; ntp++) {
                const uint32_t va = sb + (ks * 16 + (lid & 15)) * STRB
                                  + (ntp * 16 + ((lid >> 4) << 3)) * 2;
                uint32_t bh0, bh1, bh2, bh3, bl0, bl1, bl2, bl3;
                LDMX4T(bh0, bh1, bh2, bh3, va + OFF_VHI);
                LDMX4T(bl0, bl1, bl2, bl3, va + OFF_VLO);
                uint32_t bhA[2] = {bh0, bh1}, bhB[2] = {bh2, bh3};
                uint32_t blA[2] = {bl0, bl1}, blB[2] = {bl2, bl3};
                mma_bf16(oacc[2 * ntp + 0], aHi, bhA);
                mma_bf16(oacc[2 * ntp + 0], aHi, blA);
                mma_bf16(oacc[2 * ntp + 0], aLo, bhA);
                mma_bf16(oacc[2 * ntp + 1], aHi, bhB);
                mma_bf16(oacc[2 * ntp + 1], aHi, blB);
                mma_bf16(oacc[2 * ntp + 1], aLo, bhB);
            }
        }
    }

    // ---- normalize + store (bf16 hi/lo) ----
    const float rl0 = 1.f / l0, rl1 = 1.f / l1;
    const size_t row0 = (size_t)(b * SEQ + q0 + w * 16 + rq);
#pragma unroll
    for (int nt = 0; nt < 16; nt++) {
        int col = h * HDIM + nt * 8 + cq * 2;
        float v00 = oacc[nt][0] * rl0, v01 = oacc[nt][1] * rl0;
        float v10 = oacc[nt][2] * rl1, v11 = oacc[nt][3] * rl1;
        __nv_bfloat16 h00 = __float2bfloat16(v00), h01 = __float2bfloat16(v01);
        __nv_bfloat16 h10 = __float2bfloat16(v10), h11 = __float2bfloat16(v11);
        *(__nv_bfloat162*)&Ohi[row0 * HID + col] = __nv_bfloat162(h00, h01);
        *(__nv_bfloat162*)&Ohi[(row0 + 8) * HID + col] = __nv_bfloat162(h10, h11);
        *(__nv_bfloat162*)&Olo[row0 * HID + col] =
            __nv_bfloat162(__float2bfloat16(v00 - __bfloat162float(h00)),
                           __float2bfloat16(v01 - __bfloat162float(h01)));
        *(__nv_bfloat162*)&Olo[(row0 + 8) * HID + col] =
            __nv_bfloat162(__float2bfloat16(v10 - __bfloat162float(h10)),
                           __float2bfloat16(v11 - __bfloat162float(h11)));
    }
}

// ---------------------------------------------------------------------------
// Launch
// ---------------------------------------------------------------------------
extern "C" void kernel_launch(void* const* d_in, const int* in_sizes, int n_in,
                              void* d_out, int out_size)
{
    const float* x  = (const float*)d_in[0];
    const float* Wq = (const float*)d_in[2];
    const float* bq = (const float*)d_in[3];
    const float* Wk = (const float*)d_in[4];
    const float* bk = (const float*)d_in[5];
    const float* Wv = (const float*)d_in[6];
    const float* bv = (const float*)d_in[7];
    const float* Wo = (const float*)d_in[8];
    const float* bo = (const float*)d_in[9];
    float* out = (float*)d_out;

    __nv_bfloat16 *Xhi, *Xlo, *Qhi, *Qlo, *Khi, *Klo, *Vhi, *Vlo, *AOhi, *AOlo;
    __nv_bfloat16 *WqThi, *WqTlo, *WkThi, *WkTlo, *WvThi, *WvTlo, *WoThi, *WoTlo;
    cudaGetSymbolAddress((void**)&Xhi, g_Xhi);
    cudaGetSymbolAddress((void**)&Xlo, g_Xlo);
    cudaGetSymbolAddress((void**)&Qhi, g_Qhi);
    cudaGetSymbolAddress((void**)&Qlo, g_Qlo);
    cudaGetSymbolAddress((void**)&Khi, g_Khi);
    cudaGetSymbolAddress((void**)&Klo, g_Klo);
    cudaGetSymbolAddress((void**)&Vhi, g_Vhi);
    cudaGetSymbolAddress((void**)&Vlo, g_Vlo);
    cudaGetSymbolAddress((void**)&AOhi, g_AOhi);
    cudaGetSymbolAddress((void**)&AOlo, g_AOlo);
    cudaGetSymbolAddress((void**)&WqThi, g_WqThi);
    cudaGetSymbolAddress((void**)&WqTlo, g_WqTlo);
    cudaGetSymbolAddress((void**)&WkThi, g_WkThi);
    cudaGetSymbolAddress((void**)&WkTlo, g_WkTlo);
    cudaGetSymbolAddress((void**)&WvThi, g_WvThi);
    cudaGetSymbolAddress((void**)&WvTlo, g_WvTlo);
    cudaGetSymbolAddress((void**)&WoThi, g_WoThi);
    cudaGetSymbolAddress((void**)&WoTlo, g_WoTlo);

    cudaFuncSetAttribute(mma_gemm_kernel<true>,
                         cudaFuncAttributeMaxDynamicSharedMemorySize, GEMM_SMEM);
    cudaFuncSetAttribute(mma_gemm_kernel<false>,
                         cudaFuncAttributeMaxDynamicSharedMemorySize, GEMM_SMEM);
    cudaFuncSetAttribute(flash_mma_kernel,
                         cudaFuncAttributeMaxDynamicSharedMemorySize, FLASH_SMEM);

    dim3 blk(256);

    // 1) prep
    split_kernel<<<(MROWS * HID / 4 + 255) / 256, 256>>>(x, Xhi, Xlo, MROWS * HID / 4);
    transpose_split_kernel<<<dim3(HID / 32, HID / 32), 256>>>(Wq, WqThi, WqTlo, HID, HID);
    transpose_split_kernel<<<dim3(KVDIM / 32, HID / 32), 256>>>(Wk, WkThi, WkTlo, HID, KVDIM);
    transpose_split_kernel<<<dim3(KVDIM / 32, HID / 32), 256>>>(Wv, WvThi, WvTlo, HID, KVDIM);
    transpose_split_kernel<<<dim3(HID / 32, HID / 32), 256>>>(Wo, WoThi, WoTlo, HID, HID);

    // 2) projections -> bf16 hi/lo directly
    mma_gemm_kernel<true><<<dim3(HID / 128, MROWS / 128), blk, GEMM_SMEM>>>(
        Xhi, Xlo, WqThi, WqTlo, bq, nullptr, Qhi, Qlo, HID, HID);
    mma_gemm_kernel<true><<<dim3(KVDIM / 128, MROWS / 128), blk, GEMM_SMEM>>>(
        Xhi, Xlo, WkThi, WkTlo, bk, nullptr, Khi, Klo, KVDIM, HID);
    mma_gemm_kernel<true><<<dim3(KVDIM / 128, MROWS / 128), blk, GEMM_SMEM>>>(
        Xhi, Xlo, WvThi, WvTlo, bv, nullptr, Vhi, Vlo, KVDIM, HID);

    // 3) attention (HMMA)
    flash_mma_kernel<<<dim3(SEQ / QT, NHEADS, BATCH), blk, FLASH_SMEM>>>(
        Qhi, Qlo, Khi, Klo, Vhi, Vlo, AOhi, AOlo);

    // 4) output projection -> fp32 out
    mma_gemm_kernel<false><<<dim3(HID / 128, MROWS / 128), blk, GEMM_SMEM>>>(
        AOhi, AOlo, WoThi, WoTlo, bo, out, nullptr, nullptr, HID, HID);
}